// round 8
// baseline (speedup 1.0000x reference)
#include <cuda_runtime.h>
#include <cuda_bf16.h>
#include <cstdint>

// PatchEmbeder via mma.sync bf16 (split hi/lo) + affine collapse.
// out[b,0,:]   = cls + pos[0]                                  (prep kernel)
// out[b,p+1,:] = x_patch @ W1 @ (W2@W3) + beff + pos[p+1]      (main kernel)
// x[b,p,k] = inputs[b, k/256, p, (k%256)/16, k%16]
// B=128, P=196 -> 25088 rows = 392 CTAs x 64 rows. K1=768, N1=32(=K2), E=768.
//
// R8: barrier-free G1 with warp-private cp.async double-buffered staging of
// raw fp32 X; A-fragments built from LDS.64 + in-register hi/lo split.

#define THREADS 128
#define ROWSTR  528              // staging row stride bytes (132 floats)
#define BUFSZ   (16 * ROWSTR)    // 8448 B per buffer
#define WSLOT   (2 * BUFSZ)      // 16896 B per warp

// ---- device scratch (rebuilt every replay by prep_kernel) ----
__device__ __align__(16) uint4 g_W1F [6 * 8 * 4 * 32];  // [k-tile 48][n-tile 4][lane]
__device__ __align__(16) uint4 g_W23F[96 * 2 * 32];     // [n-tile 96][k-tile 2][lane]
__device__ __align__(16) float g_beff[768];

__device__ __forceinline__ uint32_t bf2bits(__nv_bfloat162 v) {
    return *reinterpret_cast<uint32_t*>(&v);
}
__device__ __forceinline__ void split2(float a, float b, uint32_t& h, uint32_t& l) {
    __nv_bfloat162 H = __floats2bfloat162_rn(a, b);
    float ha = __bfloat162float(H.x), hb = __bfloat162float(H.y);
    __nv_bfloat162 L = __floats2bfloat162_rn(a - ha, b - hb);
    h = bf2bits(H); l = bf2bits(L);
}
__device__ __forceinline__ void mma16816(float& c0, float& c1, float& c2, float& c3,
                                         const uint32_t a[4], uint32_t b0, uint32_t b1) {
    asm("mma.sync.aligned.m16n8k16.row.col.f32.bf16.bf16.f32 "
        "{%0,%1,%2,%3}, {%4,%5,%6,%7}, {%8,%9}, {%0,%1,%2,%3};"
        : "+f"(c0), "+f"(c1), "+f"(c2), "+f"(c3)
        : "r"(a[0]), "r"(a[1]), "r"(a[2]), "r"(a[3]), "r"(b0), "r"(b1));
}
__device__ __forceinline__ uint32_t smem_u32(const void* p) {
    uint32_t a;
    asm("{ .reg .u64 t; cvta.to.shared.u64 t, %1; cvt.u32.u64 %0, t; }" : "=r"(a) : "l"(p));
    return a;
}
__device__ __forceinline__ void cp_async16(uint32_t dst, const void* src) {
    asm volatile("cp.async.cg.shared.global [%0], [%1], 16;" :: "r"(dst), "l"(src));
}
#define CP_COMMIT()  asm volatile("cp.async.commit_group;" ::: "memory")
#define CP_WAIT(N)   asm volatile("cp.async.wait_group %0;" :: "n"(N) : "memory")
__device__ __forceinline__ float2 lds64(uint32_t a) {
    float2 v;
    asm volatile("ld.shared.v2.f32 {%0,%1}, [%2];" : "=f"(v.x), "=f"(v.y) : "r"(a));
    return v;
}

// =====================================================================
// prep: bake W1 / W23=W2@W3 fragments (hi/lo), beff, cls rows.
// grid 96 x 256 = 24576 threads.
// =====================================================================
__global__ void prep_kernel(const float* __restrict__ W1, const float* __restrict__ b1,
                            const float* __restrict__ W2, const float* __restrict__ b2,
                            const float* __restrict__ W3, const float* __restrict__ b3,
                            const float* __restrict__ cls, const float* __restrict__ pos,
                            float* __restrict__ out)
{
    __shared__ float W2s[32 * 65];   // padded stride 65
    __shared__ float t1s[64];

    const int t = threadIdx.x;
    const int g = blockIdx.x * 256 + t;   // 0..24575

#pragma unroll
    for (int i = t; i < 2048; i += 256)
        W2s[(i >> 6) * 65 + (i & 63)] = __ldg(W2 + i);
    __syncthreads();

    if (t < 64) {
        float acc = __ldg(b2 + t);
#pragma unroll
        for (int i = 0; i < 32; ++i) acc += __ldg(b1 + i) * W2s[i * 65 + t];
        t1s[t] = acc;
    }
    __syncthreads();

    // ---- W1 fragments: element (k = g>>5, n = g&31) ----
    {
        const int k = g >> 5, n = g & 31;
        const float v = __ldg(W1 + k * 32 + n);
        const __nv_bfloat16 h = __float2bfloat16(v);
        const __nv_bfloat16 l = __float2bfloat16(v - __bfloat162float(h));
        const int kt = k >> 4, kin = k & 15;
        const int lane = ((n & 7) << 2) + ((kin & 7) >> 1);
        const int reg = kin >> 3, half = kin & 1;
        uint16_t* base = (uint16_t*)&g_W1F[((kt << 2) + (n >> 3)) * 32 + lane];
        base[(reg << 1) + half]     = *(const uint16_t*)&h;
        base[4 + (reg << 1) + half] = *(const uint16_t*)&l;
    }
    // ---- W23 fragments + beff: (e = g>>5, k2 = g&31) ----
    {
        const int e = g >> 5, k2 = g & 31;
        float acc = 0.f;
        float accb = (k2 == 0) ? __ldg(b3 + e) : 0.f;
#pragma unroll
        for (int j = 0; j < 64; ++j) {
            const float w3v = __ldg(W3 + j * 768 + e);   // warp-uniform broadcast
            acc += W2s[k2 * 65 + j] * w3v;
            if (k2 == 0) accb += t1s[j] * w3v;
        }
        const __nv_bfloat16 h = __float2bfloat16(acc);
        const __nv_bfloat16 l = __float2bfloat16(acc - __bfloat162float(h));
        const int kt = k2 >> 4, kin = k2 & 15;
        const int lane = ((e & 7) << 2) + ((kin & 7) >> 1);
        const int reg = kin >> 3, half = kin & 1;
        uint16_t* base = (uint16_t*)&g_W23F[(((e >> 3) << 1) + kt) * 32 + lane];
        base[(reg << 1) + half]     = *(const uint16_t*)&h;
        base[4 + (reg << 1) + half] = *(const uint16_t*)&l;
        if (k2 == 0) g_beff[e] = accb;
    }
    // ---- cls rows ----
    {
        const int e4 = g % 192, b = g / 192;
        const float4 c = __ldg((const float4*)cls + e4);
        const float4 pp = __ldg((const float4*)pos + e4);
        *((float4*)(out + (size_t)b * 197 * 768) + e4) =
            make_float4(c.x + pp.x, c.y + pp.y, c.z + pp.z, c.w + pp.w);
    }
}

// =====================================================================
// main: 392 CTAs x 128 threads (4 warps), 64 rows. Warp w owns rows
// [w*16, w*16+16) for the whole kernel; zero CTA barriers.
// smem: per-warp 2-deep ring of raw fp32 X chunks (16 rows x 132 floats).
// =====================================================================
__global__ __launch_bounds__(THREADS, 3)
void patch_embed_mma(const float* __restrict__ X, const float* __restrict__ pos,
                     float* __restrict__ out)
{
    extern __shared__ char smem[];
    const uint32_t sb = smem_u32(smem);
    const int t = threadIdx.x;
    const int w = t >> 5;
    const int ln = t & 31;
    const int r0 = blockIdx.x * 64;
    const int wr0 = w << 4;                       // warp's 16 rows
    const uint32_t wbuf = sb + (uint32_t)w * WSLOT;

    const int gr = ln >> 2;                       // fragment row 0..7
    const int q2 = (ln & 3) << 1;                 // fragment col pair base

    // precompute per-row gmem bases for this warp's 16 rows (channel added later)
    const float* rowbase[16];
#pragma unroll
    for (int lr = 0; lr < 16; ++lr) {
        const int R = r0 + wr0 + lr;
        const int b = R / 196;
        const int p = R - b * 196;
        rowbase[lr] = X + (((size_t)b * 3 * 196 + p) << 8);   // + ch*196*256 later
    }

    // ---------------- G1: H[16x32] = Xrows @ W1, cp.async pipelined ---------------
    float acc1[4][4];
#pragma unroll
    for (int i = 0; i < 4; ++i)
#pragma unroll
        for (int j = 0; j < 4; ++j) acc1[i][j] = 0.f;

    // stage chunk kc into ring slot d (raw fp32, 16 rows x 128 floats)
    auto stage = [&](int kc, int d) {
        const size_t choff = (size_t)(kc >> 1) * (196 << 8) + ((kc & 1) << 7) + (ln << 2);
        const uint32_t dst = wbuf + (uint32_t)d * BUFSZ + (uint32_t)(ln << 4);
#pragma unroll
        for (int lr = 0; lr < 16; ++lr)
            cp_async16(dst + lr * ROWSTR, rowbase[lr] + choff);
        CP_COMMIT();
    };

    auto consume = [&](int kc, int d) {
        const uint32_t buf = wbuf + (uint32_t)d * BUFSZ;
        const uint32_t a00 = buf + (uint32_t)gr * ROWSTR + (uint32_t)(q2 << 2);
#pragma unroll
        for (int kt = 0; kt < 8; ++kt) {
            const uint32_t a = a00 + (uint32_t)(kt << 6);     // kt*16 floats
            const float2 f0 = lds64(a);                       // (gr,   k-lo)
            const float2 f1 = lds64(a + 8 * ROWSTR);          // (gr+8, k-lo)
            const float2 f2 = lds64(a + 32);                  // (gr,   k-hi)
            const float2 f3 = lds64(a + 8 * ROWSTR + 32);     // (gr+8, k-hi)
            uint32_t ah[4], al[4];
            split2(f0.x, f0.y, ah[0], al[0]);
            split2(f1.x, f1.y, ah[1], al[1]);
            split2(f2.x, f2.y, ah[2], al[2]);
            split2(f3.x, f3.y, ah[3], al[3]);

            const uint4* bp = &g_W1F[(((kc << 3) + kt) << 2) * 32 + ln];
            uint4 bf[4];
#pragma unroll
            for (int nt = 0; nt < 4; ++nt) bf[nt] = __ldg(bp + nt * 32);
#pragma unroll
            for (int nt = 0; nt < 4; ++nt)
                mma16816(acc1[nt][0], acc1[nt][1], acc1[nt][2], acc1[nt][3], ah, bf[nt].x, bf[nt].y);
#pragma unroll
            for (int nt = 0; nt < 4; ++nt)
                mma16816(acc1[nt][0], acc1[nt][1], acc1[nt][2], acc1[nt][3], al, bf[nt].x, bf[nt].y);
#pragma unroll
            for (int nt = 0; nt < 4; ++nt)
                mma16816(acc1[nt][0], acc1[nt][1], acc1[nt][2], acc1[nt][3], ah, bf[nt].z, bf[nt].w);
        }
    };

    stage(0, 0);
    stage(1, 1);
#pragma unroll
    for (int c = 0; c < 6; ++c) {
        if (c < 5) { CP_WAIT(1); } else { CP_WAIT(0); }
        __syncwarp();
        consume(c, c & 1);
        if (c < 4) stage(c + 2, c & 1);
    }

    // ---------------- H fragments -> G23 A fragments (thread-local remap) ----------
    uint32_t Ah[2][4], Al[2][4];
#pragma unroll
    for (int q = 0; q < 2; ++q) {
        split2(acc1[2*q][0],   acc1[2*q][1],   Ah[q][0], Al[q][0]);
        split2(acc1[2*q][2],   acc1[2*q][3],   Ah[q][1], Al[q][1]);
        split2(acc1[2*q+1][0], acc1[2*q+1][1], Ah[q][2], Al[q][2]);
        split2(acc1[2*q+1][2], acc1[2*q+1][3], Ah[q][3], Al[q][3]);
    }

    // ---------------- G23: out rows = H @ W23 + beff + pos, fused epilogue ---------
    const int rA = r0 + wr0 + gr;
    const int bA = rA / 196, pA = rA - bA * 196;
    const int rB = rA + 8;
    const int bB = rB / 196, pB = rB - bB * 196;
    float* const orowA = out + ((size_t)bA * 197 + pA + 1) * 768;
    float* const orowB = out + ((size_t)bB * 197 + pB + 1) * 768;
    const float* const prowA = pos + (pA + 1) * 768;
    const float* const prowB = pos + (pB + 1) * 768;
    const int ncol = q2;

#pragma unroll 4
    for (int nt = 0; nt < 96; ++nt) {
        const uint4 b0 = __ldg(&g_W23F[((nt << 1) + 0) * 32 + ln]);
        const uint4 b1 = __ldg(&g_W23F[((nt << 1) + 1) * 32 + ln]);
        float h0 = 0.f, h1 = 0.f, h2 = 0.f, h3 = 0.f;   // Ah*Bh
        float g0 = 0.f, g1 = 0.f, g2 = 0.f, g3 = 0.f;   // Ah*Bl
        float l0 = 0.f, l1 = 0.f, l2 = 0.f, l3 = 0.f;   // Al*Bh
        mma16816(h0, h1, h2, h3, Ah[0], b0.x, b0.y);
        mma16816(g0, g1, g2, g3, Ah[0], b0.z, b0.w);
        mma16816(l0, l1, l2, l3, Al[0], b0.x, b0.y);
        mma16816(h0, h1, h2, h3, Ah[1], b1.x, b1.y);
        mma16816(g0, g1, g2, g3, Ah[1], b1.z, b1.w);
        mma16816(l0, l1, l2, l3, Al[1], b1.x, b1.y);

        const int n = (nt << 3) + ncol;
        const float2 be = __ldg((const float2*)(g_beff + n));
        const float2 pa = __ldg((const float2*)(prowA + n));
        const float2 pb = __ldg((const float2*)(prowB + n));
        *(float2*)(orowA + n) = make_float2((h0 + g0) + (l0 + be.x + pa.x),
                                            (h1 + g1) + (l1 + be.y + pa.y));
        *(float2*)(orowB + n) = make_float2((h2 + g2) + (l2 + be.x + pb.x),
                                            (h3 + g3) + (l3 + be.y + pb.y));
    }
}

extern "C" void kernel_launch(void* const* d_in, const int* in_sizes, int n_in,
                              void* d_out, int out_size)
{
    const float* X   = (const float*)d_in[0];
    const float* W1  = (const float*)d_in[1];
    const float* b1  = (const float*)d_in[2];
    const float* W2  = (const float*)d_in[3];
    const float* b2  = (const float*)d_in[4];
    const float* W3  = (const float*)d_in[5];
    const float* b3  = (const float*)d_in[6];
    const float* cls = (const float*)d_in[7];
    const float* pos = (const float*)d_in[8];
    float* out = (float*)d_out;

    const int smem = 4 * WSLOT;   // 67584 B
    cudaFuncSetAttribute(patch_embed_mma,
                         cudaFuncAttributeMaxDynamicSharedMemorySize, smem);

    prep_kernel<<<96, 256>>>(W1, b1, W2, b2, W3, b3, cls, pos, out);
    patch_embed_mma<<<392, THREADS, smem>>>(X, pos, out);
}

// round 9
// speedup vs baseline: 1.1395x; 1.1395x over previous
#include <cuda_runtime.h>
#include <cuda_bf16.h>
#include <cstdint>

// PatchEmbeder via mma.sync bf16 (split hi/lo) + affine collapse.
// out[b,0,:]   = cls + pos[0]                                  (prep kernel)
// out[b,p+1,:] = x_patch @ W1 @ (W2@W3) + beff + pos[p+1]      (main kernel)
// x[b,p,k] = inputs[b, k/256, p, (k%256)/16, k%16]
// B=128, P=196 -> 25088 rows = 392 CTAs x 64 rows. K1=768, N1=32(=K2), E=768.
//
// R9: G23 epilogue de-scatter. mma results staged per n-group (128 cols) in a
// per-warp smem tile, then written out with fully coalesced float4 row stores.
// (R8 analysis: epilogue 32B-scatter made the kernel L1tex-wavefront-bound.)

#define THREADS 128
#define ROWSTR  528              // staging/result row stride bytes (132 floats)
#define BUFSZ   (16 * ROWSTR)    // 8448 B per buffer
#define WSLOT   (2 * BUFSZ)      // 16896 B per warp

// ---- device scratch (rebuilt every replay by prep_kernel) ----
__device__ __align__(16) uint4 g_W1F [6 * 8 * 4 * 32];  // [k-tile 48][n-tile 4][lane]
__device__ __align__(16) uint4 g_W23F[96 * 2 * 32];     // [n-tile 96][k-tile 2][lane]
__device__ __align__(16) float g_beff[768];

__device__ __forceinline__ uint32_t bf2bits(__nv_bfloat162 v) {
    return *reinterpret_cast<uint32_t*>(&v);
}
__device__ __forceinline__ void split2(float a, float b, uint32_t& h, uint32_t& l) {
    __nv_bfloat162 H = __floats2bfloat162_rn(a, b);
    float ha = __bfloat162float(H.x), hb = __bfloat162float(H.y);
    __nv_bfloat162 L = __floats2bfloat162_rn(a - ha, b - hb);
    h = bf2bits(H); l = bf2bits(L);
}
__device__ __forceinline__ void mma16816(float& c0, float& c1, float& c2, float& c3,
                                         const uint32_t a[4], uint32_t b0, uint32_t b1) {
    asm("mma.sync.aligned.m16n8k16.row.col.f32.bf16.bf16.f32 "
        "{%0,%1,%2,%3}, {%4,%5,%6,%7}, {%8,%9}, {%0,%1,%2,%3};"
        : "+f"(c0), "+f"(c1), "+f"(c2), "+f"(c3)
        : "r"(a[0]), "r"(a[1]), "r"(a[2]), "r"(a[3]), "r"(b0), "r"(b1));
}
__device__ __forceinline__ uint32_t smem_u32(const void* p) {
    uint32_t a;
    asm("{ .reg .u64 t; cvta.to.shared.u64 t, %1; cvt.u32.u64 %0, t; }" : "=r"(a) : "l"(p));
    return a;
}
__device__ __forceinline__ void cp_async16(uint32_t dst, const void* src) {
    asm volatile("cp.async.cg.shared.global [%0], [%1], 16;" :: "r"(dst), "l"(src));
}
#define CP_COMMIT()  asm volatile("cp.async.commit_group;" ::: "memory")
#define CP_WAIT(N)   asm volatile("cp.async.wait_group %0;" :: "n"(N) : "memory")
__device__ __forceinline__ float2 lds64(uint32_t a) {
    float2 v;
    asm volatile("ld.shared.v2.f32 {%0,%1}, [%2];" : "=f"(v.x), "=f"(v.y) : "r"(a));
    return v;
}
__device__ __forceinline__ void sts64(uint32_t a, float x, float y) {
    asm volatile("st.shared.v2.f32 [%0], {%1,%2};" :: "r"(a), "f"(x), "f"(y));
}
__device__ __forceinline__ float4 lds128(uint32_t a) {
    float4 v;
    asm volatile("ld.shared.v4.f32 {%0,%1,%2,%3}, [%4];"
                 : "=f"(v.x), "=f"(v.y), "=f"(v.z), "=f"(v.w) : "r"(a));
    return v;
}

// =====================================================================
// prep: bake W1 / W23=W2@W3 fragments (hi/lo), beff, cls rows.
// grid 96 x 256 = 24576 threads.
// =====================================================================
__global__ void prep_kernel(const float* __restrict__ W1, const float* __restrict__ b1,
                            const float* __restrict__ W2, const float* __restrict__ b2,
                            const float* __restrict__ W3, const float* __restrict__ b3,
                            const float* __restrict__ cls, const float* __restrict__ pos,
                            float* __restrict__ out)
{
    __shared__ float W2s[32 * 65];   // padded stride 65
    __shared__ float t1s[64];

    const int t = threadIdx.x;
    const int g = blockIdx.x * 256 + t;   // 0..24575

#pragma unroll
    for (int i = t; i < 2048; i += 256)
        W2s[(i >> 6) * 65 + (i & 63)] = __ldg(W2 + i);
    __syncthreads();

    if (t < 64) {
        float acc = __ldg(b2 + t);
#pragma unroll
        for (int i = 0; i < 32; ++i) acc += __ldg(b1 + i) * W2s[i * 65 + t];
        t1s[t] = acc;
    }
    __syncthreads();

    // ---- W1 fragments: element (k = g>>5, n = g&31) ----
    {
        const int k = g >> 5, n = g & 31;
        const float v = __ldg(W1 + k * 32 + n);
        const __nv_bfloat16 h = __float2bfloat16(v);
        const __nv_bfloat16 l = __float2bfloat16(v - __bfloat162float(h));
        const int kt = k >> 4, kin = k & 15;
        const int lane = ((n & 7) << 2) + ((kin & 7) >> 1);
        const int reg = kin >> 3, half = kin & 1;
        uint16_t* base = (uint16_t*)&g_W1F[((kt << 2) + (n >> 3)) * 32 + lane];
        base[(reg << 1) + half]     = *(const uint16_t*)&h;
        base[4 + (reg << 1) + half] = *(const uint16_t*)&l;
    }
    // ---- W23 fragments + beff: (e = g>>5, k2 = g&31) ----
    {
        const int e = g >> 5, k2 = g & 31;
        float acc = 0.f;
        float accb = (k2 == 0) ? __ldg(b3 + e) : 0.f;
#pragma unroll
        for (int j = 0; j < 64; ++j) {
            const float w3v = __ldg(W3 + j * 768 + e);   // warp-uniform broadcast
            acc += W2s[k2 * 65 + j] * w3v;
            if (k2 == 0) accb += t1s[j] * w3v;
        }
        const __nv_bfloat16 h = __float2bfloat16(acc);
        const __nv_bfloat16 l = __float2bfloat16(acc - __bfloat162float(h));
        const int kt = k2 >> 4, kin = k2 & 15;
        const int lane = ((e & 7) << 2) + ((kin & 7) >> 1);
        const int reg = kin >> 3, half = kin & 1;
        uint16_t* base = (uint16_t*)&g_W23F[(((e >> 3) << 1) + kt) * 32 + lane];
        base[(reg << 1) + half]     = *(const uint16_t*)&h;
        base[4 + (reg << 1) + half] = *(const uint16_t*)&l;
        if (k2 == 0) g_beff[e] = accb;
    }
    // ---- cls rows ----
    {
        const int e4 = g % 192, b = g / 192;
        const float4 c = __ldg((const float4*)cls + e4);
        const float4 pp = __ldg((const float4*)pos + e4);
        *((float4*)(out + (size_t)b * 197 * 768) + e4) =
            make_float4(c.x + pp.x, c.y + pp.y, c.z + pp.z, c.w + pp.w);
    }
}

// =====================================================================
// main: 392 CTAs x 128 threads (4 warps), 64 rows. Warp w owns rows
// [w*16, w*16+16) for the whole kernel; zero CTA barriers.
// smem: per-warp 2-deep ring; slot0 doubles as the G23 result tile.
// =====================================================================
__global__ __launch_bounds__(THREADS, 3)
void patch_embed_mma(const float* __restrict__ X, const float* __restrict__ pos,
                     float* __restrict__ out)
{
    extern __shared__ char smem[];
    const uint32_t sb = smem_u32(smem);
    const int t = threadIdx.x;
    const int w = t >> 5;
    const int ln = t & 31;
    const int r0 = blockIdx.x * 64;
    const int wr0 = w << 4;                       // warp's 16 rows
    const uint32_t wbuf = sb + (uint32_t)w * WSLOT;

    const int gr = ln >> 2;                       // fragment row 0..7
    const int q2 = (ln & 3) << 1;                 // fragment col pair base

    // per-row gmem bases for this warp's 16 rows (channel offset added later)
    const float* rowbase[16];
#pragma unroll
    for (int lr = 0; lr < 16; ++lr) {
        const int R = r0 + wr0 + lr;
        const int b = R / 196;
        const int p = R - b * 196;
        rowbase[lr] = X + (((size_t)b * 3 * 196 + p) << 8);
    }

    // ---------------- G1: H[16x32] = Xrows @ W1, cp.async pipelined ---------------
    float acc1[4][4];
#pragma unroll
    for (int i = 0; i < 4; ++i)
#pragma unroll
        for (int j = 0; j < 4; ++j) acc1[i][j] = 0.f;

    auto stage = [&](int kc, int d) {
        const size_t choff = (size_t)(kc >> 1) * (196 << 8) + ((kc & 1) << 7) + (ln << 2);
        const uint32_t dst = wbuf + (uint32_t)d * BUFSZ + (uint32_t)(ln << 4);
#pragma unroll
        for (int lr = 0; lr < 16; ++lr)
            cp_async16(dst + lr * ROWSTR, rowbase[lr] + choff);
        CP_COMMIT();
    };

    auto consume = [&](int kc, int d) {
        const uint32_t buf = wbuf + (uint32_t)d * BUFSZ;
        const uint32_t a00 = buf + (uint32_t)gr * ROWSTR + (uint32_t)(q2 << 2);
#pragma unroll
        for (int kt = 0; kt < 8; ++kt) {
            const uint32_t a = a00 + (uint32_t)(kt << 6);     // kt*16 floats
            const float2 f0 = lds64(a);                       // (gr,   k-lo)
            const float2 f1 = lds64(a + 8 * ROWSTR);          // (gr+8, k-lo)
            const float2 f2 = lds64(a + 32);                  // (gr,   k-hi)
            const float2 f3 = lds64(a + 8 * ROWSTR + 32);     // (gr+8, k-hi)
            uint32_t ah[4], al[4];
            split2(f0.x, f0.y, ah[0], al[0]);
            split2(f1.x, f1.y, ah[1], al[1]);
            split2(f2.x, f2.y, ah[2], al[2]);
            split2(f3.x, f3.y, ah[3], al[3]);

            const uint4* bp = &g_W1F[(((kc << 3) + kt) << 2) * 32 + ln];
            uint4 bf[4];
#pragma unroll
            for (int nt = 0; nt < 4; ++nt) bf[nt] = __ldg(bp + nt * 32);
#pragma unroll
            for (int nt = 0; nt < 4; ++nt)
                mma16816(acc1[nt][0], acc1[nt][1], acc1[nt][2], acc1[nt][3], ah, bf[nt].x, bf[nt].y);
#pragma unroll
            for (int nt = 0; nt < 4; ++nt)
                mma16816(acc1[nt][0], acc1[nt][1], acc1[nt][2], acc1[nt][3], al, bf[nt].x, bf[nt].y);
#pragma unroll
            for (int nt = 0; nt < 4; ++nt)
                mma16816(acc1[nt][0], acc1[nt][1], acc1[nt][2], acc1[nt][3], ah, bf[nt].z, bf[nt].w);
        }
    };

    stage(0, 0);
    stage(1, 1);
#pragma unroll
    for (int c = 0; c < 6; ++c) {
        if (c < 5) { CP_WAIT(1); } else { CP_WAIT(0); }
        __syncwarp();
        consume(c, c & 1);
        if (c < 4) stage(c + 2, c & 1);
    }
    CP_WAIT(0);
    __syncwarp();

    // ---------------- H fragments -> G23 A fragments (thread-local remap) ----------
    uint32_t Ah[2][4], Al[2][4];
#pragma unroll
    for (int q = 0; q < 2; ++q) {
        split2(acc1[2*q][0],   acc1[2*q][1],   Ah[q][0], Al[q][0]);
        split2(acc1[2*q][2],   acc1[2*q][3],   Ah[q][1], Al[q][1]);
        split2(acc1[2*q+1][0], acc1[2*q+1][1], Ah[q][2], Al[q][2]);
        split2(acc1[2*q+1][2], acc1[2*q+1][3], Ah[q][3], Al[q][3]);
    }

    // ---------------- G23: 6 groups of 16 n-tiles (128 cols), smem-staged epilogue --
    const uint32_t rbuf = wbuf;                       // result tile: 16 rows x 132 floats
    const uint32_t stsA = rbuf + (uint32_t)gr * ROWSTR + (uint32_t)(q2 << 2);
    const uint32_t stsB = stsA + 8 * ROWSTR;

    for (int gidx = 0; gidx < 6; ++gidx) {
        // mma over the group's 16 tiles, results -> smem tile
#pragma unroll 4
        for (int tt = 0; tt < 16; ++tt) {
            const int nt = gidx * 16 + tt;
            const uint4 b0 = __ldg(&g_W23F[((nt << 1) + 0) * 32 + ln]);
            const uint4 b1 = __ldg(&g_W23F[((nt << 1) + 1) * 32 + ln]);
            float h0 = 0.f, h1 = 0.f, h2 = 0.f, h3 = 0.f;   // Ah*Bh
            float g0 = 0.f, g1 = 0.f, g2 = 0.f, g3 = 0.f;   // Ah*Bl
            float l0 = 0.f, l1 = 0.f, l2 = 0.f, l3 = 0.f;   // Al*Bh
            mma16816(h0, h1, h2, h3, Ah[0], b0.x, b0.y);
            mma16816(g0, g1, g2, g3, Ah[0], b0.z, b0.w);
            mma16816(l0, l1, l2, l3, Al[0], b0.x, b0.y);
            mma16816(h0, h1, h2, h3, Ah[1], b1.x, b1.y);
            mma16816(g0, g1, g2, g3, Ah[1], b1.z, b1.w);
            mma16816(l0, l1, l2, l3, Al[1], b1.x, b1.y);

            const uint32_t coff = (uint32_t)(tt << 5);       // tt*8 floats
            sts64(stsA + coff, h0 + g0 + l0, h1 + g1 + l1);
            sts64(stsB + coff, h2 + g2 + l2, h3 + g3 + l3);
        }
        __syncwarp();

        // coalesced write-out: one full row (128 cols) per instruction
        const int gcol = gidx * 128 + (ln << 2);
        const float4 be = __ldg((const float4*)(g_beff + gcol));
        const uint32_t rdbase = rbuf + (uint32_t)(ln << 4);
#pragma unroll
        for (int lr = 0; lr < 16; ++lr) {
            const int R = r0 + wr0 + lr;
            const int b = R / 196;
            const int p = R - b * 196;
            const float4 rv = lds128(rdbase + (uint32_t)lr * ROWSTR);
            const float4 pv = __ldg((const float4*)(pos + (p + 1) * 768 + gcol));
            float4 o;
            o.x = rv.x + pv.x + be.x;
            o.y = rv.y + pv.y + be.y;
            o.z = rv.z + pv.z + be.z;
            o.w = rv.w + pv.w + be.w;
            *(float4*)(out + ((size_t)b * 197 + p + 1) * 768 + gcol) = o;
        }
        __syncwarp();   // protect tile before next group's STS
    }
}

extern "C" void kernel_launch(void* const* d_in, const int* in_sizes, int n_in,
                              void* d_out, int out_size)
{
    const float* X   = (const float*)d_in[0];
    const float* W1  = (const float*)d_in[1];
    const float* b1  = (const float*)d_in[2];
    const float* W2  = (const float*)d_in[3];
    const float* b2  = (const float*)d_in[4];
    const float* W3  = (const float*)d_in[5];
    const float* b3  = (const float*)d_in[6];
    const float* cls = (const float*)d_in[7];
    const float* pos = (const float*)d_in[8];
    float* out = (float*)d_out;

    const int smem = 4 * WSLOT;   // 67584 B
    cudaFuncSetAttribute(patch_embed_mma,
                         cudaFuncAttributeMaxDynamicSharedMemorySize, smem);

    prep_kernel<<<96, 256>>>(W1, b1, W2, b2, W3, b3, cls, pos, out);
    patch_embed_mma<<<392, THREADS, smem>>>(X, pos, out);
}

// round 10
// speedup vs baseline: 1.2472x; 1.0945x over previous
#include <cuda_runtime.h>
#include <cuda_bf16.h>
#include <cstdint>

// PatchEmbeder via mma.sync tf32 m16n8k8 + affine collapse.
// out[b,0,:]   = cls + pos[0]                                  (prep kernel)
// out[b,p+1,:] = x_patch @ W1 @ (W2@W3) + beff + pos[p+1]      (main kernel)
// x[b,p,k] = inputs[b, k/256, p, (k%256)/16, k%16]
// B=128, P=196 -> 25088 rows = 392 CTAs x 64 rows. K1=768, N1=32(=K2), E=768.
//
// R10: tf32 replaces split-bf16 (3-term) -> 33% fewer mma, ~70% less convert
// work per warp. Latency-bound kernel => time ~ instructions/warp.

#define THREADS 128
#define ROWSTR  528              // staging/result row stride bytes (132 words, ==4 mod 32)
#define BUFSZ   (16 * ROWSTR)    // 8448 B per buffer
#define WSLOT   (2 * BUFSZ)      // 16896 B per warp

// ---- device scratch (rebuilt every replay by prep_kernel) ----
// tf32 fragment weights for mma.sync m16n8k8 (B operand), kt8 pairs packed:
//   uint4 per lane: {b0_even, b1_even, b0_odd, b1_odd}
__device__ __align__(16) uint4 g_W1F [48 * 4 * 32];   // [kt16 48][nt 4][lane]
__device__ __align__(16) uint4 g_W23F[96 * 2 * 32];   // [nt 96][kt8-pair 2][lane]
__device__ __align__(16) float g_beff[768];

__device__ __forceinline__ uint32_t f2tf32(float f) {
    uint32_t r;
    asm("cvt.rna.tf32.f32 %0, %1;" : "=r"(r) : "f"(f));
    return r;
}
__device__ __forceinline__ void mma_tf32(float* c, const uint32_t a[4],
                                         uint32_t b0, uint32_t b1) {
    asm("mma.sync.aligned.m16n8k8.row.col.f32.tf32.tf32.f32 "
        "{%0,%1,%2,%3}, {%4,%5,%6,%7}, {%8,%9}, {%0,%1,%2,%3};"
        : "+f"(c[0]), "+f"(c[1]), "+f"(c[2]), "+f"(c[3])
        : "r"(a[0]), "r"(a[1]), "r"(a[2]), "r"(a[3]), "r"(b0), "r"(b1));
}
__device__ __forceinline__ uint32_t smem_u32(const void* p) {
    uint32_t a;
    asm("{ .reg .u64 t; cvta.to.shared.u64 t, %1; cvt.u32.u64 %0, t; }" : "=r"(a) : "l"(p));
    return a;
}
__device__ __forceinline__ void cp_async16(uint32_t dst, const void* src) {
    asm volatile("cp.async.cg.shared.global [%0], [%1], 16;" :: "r"(dst), "l"(src));
}
#define CP_COMMIT()  asm volatile("cp.async.commit_group;" ::: "memory")
#define CP_WAIT(N)   asm volatile("cp.async.wait_group %0;" :: "n"(N) : "memory")
__device__ __forceinline__ float lds32(uint32_t a) {
    float v;
    asm volatile("ld.shared.f32 %0, [%1];" : "=f"(v) : "r"(a));
    return v;
}
__device__ __forceinline__ void sts64(uint32_t a, float x, float y) {
    asm volatile("st.shared.v2.f32 [%0], {%1,%2};" :: "r"(a), "f"(x), "f"(y));
}
__device__ __forceinline__ float4 lds128(uint32_t a) {
    float4 v;
    asm volatile("ld.shared.v4.f32 {%0,%1,%2,%3}, [%4];"
                 : "=f"(v.x), "=f"(v.y), "=f"(v.z), "=f"(v.w) : "r"(a));
    return v;
}

// =====================================================================
// prep: bake W1 / W23=W2@W3 tf32 fragments, beff, cls rows.
// grid 96 x 256 = 24576 threads.
// =====================================================================
__global__ void prep_kernel(const float* __restrict__ W1, const float* __restrict__ b1,
                            const float* __restrict__ W2, const float* __restrict__ b2,
                            const float* __restrict__ W3, const float* __restrict__ b3,
                            const float* __restrict__ cls, const float* __restrict__ pos,
                            float* __restrict__ out)
{
    __shared__ float W2s[32 * 65];   // padded stride 65
    __shared__ float t1s[64];

    const int t = threadIdx.x;
    const int g = blockIdx.x * 256 + t;   // 0..24575

#pragma unroll
    for (int i = t; i < 2048; i += 256)
        W2s[(i >> 6) * 65 + (i & 63)] = __ldg(W2 + i);
    __syncthreads();

    if (t < 64) {
        float acc = __ldg(b2 + t);
#pragma unroll
        for (int i = 0; i < 32; ++i) acc += __ldg(b1 + i) * W2s[i * 65 + t];
        t1s[t] = acc;
    }
    __syncthreads();

    // ---- W1 fragment element (k = g>>5 in 0..767, n = g&31), tf32 ----
    {
        const int k = g >> 5, n = g & 31;
        const uint32_t tv = f2tf32(__ldg(W1 + k * 32 + n));
        const int kt16 = k >> 4;
        const int comp = (((k >> 3) & 1) << 1) | ((k & 7) >> 2);
        const int lane = ((n & 7) << 2) | (k & 3);
        const int nt = n >> 3;
        ((uint32_t*)&g_W1F[(kt16 * 4 + nt) * 32 + lane])[comp] = tv;
    }
    // ---- W23 fragment + beff: (e = g>>5, k2 = g&31) ----
    {
        const int e = g >> 5, k2 = g & 31;
        float acc = 0.f;
        float accb = (k2 == 0) ? __ldg(b3 + e) : 0.f;
#pragma unroll
        for (int j = 0; j < 64; ++j) {
            const float w3v = __ldg(W3 + j * 768 + e);   // warp-uniform broadcast
            acc += W2s[k2 * 65 + j] * w3v;
            if (k2 == 0) accb += t1s[j] * w3v;
        }
        const uint32_t tv = f2tf32(acc);
        const int nt = e >> 3, pair = k2 >> 4;
        const int comp = (((k2 >> 3) & 1) << 1) | ((k2 & 7) >> 2);
        const int lane = ((e & 7) << 2) | (k2 & 3);
        ((uint32_t*)&g_W23F[(nt * 2 + pair) * 32 + lane])[comp] = tv;
        if (k2 == 0) g_beff[e] = accb;
    }
    // ---- cls rows ----
    {
        const int e4 = g % 192, b = g / 192;
        const float4 c = __ldg((const float4*)cls + e4);
        const float4 pp = __ldg((const float4*)pos + e4);
        *((float4*)(out + (size_t)b * 197 * 768) + e4) =
            make_float4(c.x + pp.x, c.y + pp.y, c.z + pp.z, c.w + pp.w);
    }
}

// =====================================================================
// main: 392 CTAs x 128 threads (4 warps), 64 rows. Warp w owns rows
// [w*16, w*16+16); zero CTA barriers. Per-warp 2-deep cp.async ring of
// raw fp32 X chunks; slot doubles as the G23 result tile.
// =====================================================================
__global__ __launch_bounds__(THREADS, 3)
void patch_embed_mma(const float* __restrict__ X, const float* __restrict__ pos,
                     float* __restrict__ out)
{
    extern __shared__ char smem[];
    const uint32_t sb = smem_u32(smem);
    const int t = threadIdx.x;
    const int w = t >> 5;
    const int ln = t & 31;
    const int r0 = blockIdx.x * 64;
    const int wr0 = w << 4;                       // warp's 16 rows
    const uint32_t wbuf = sb + (uint32_t)w * WSLOT;

    const int gr = ln >> 2;                       // fragment row 0..7
    const int q2 = (ln & 3) << 1;                 // C-fragment col pair base

    // per-row gmem bases for this warp's 16 rows (channel offset added later)
    const float* rowbase[16];
#pragma unroll
    for (int lr = 0; lr < 16; ++lr) {
        const int R = r0 + wr0 + lr;
        const int b = R / 196;
        const int p = R - b * 196;
        rowbase[lr] = X + (((size_t)b * 3 * 196 + p) << 8);
    }

    // ---------------- G1: H[16x32] = Xrows @ W1, tf32, cp.async pipelined ----------
    float acc1[4][4];
#pragma unroll
    for (int i = 0; i < 4; ++i)
#pragma unroll
        for (int j = 0; j < 4; ++j) acc1[i][j] = 0.f;

    auto stage = [&](int kc, int d) {
        const size_t choff = (size_t)(kc >> 1) * (196 << 8) + ((kc & 1) << 7) + (ln << 2);
        const uint32_t dst = wbuf + (uint32_t)d * BUFSZ + (uint32_t)(ln << 4);
#pragma unroll
        for (int lr = 0; lr < 16; ++lr)
            cp_async16(dst + lr * ROWSTR, rowbase[lr] + choff);
        CP_COMMIT();
    };

    auto consume = [&](int kc, int d) {
        const uint32_t buf = wbuf + (uint32_t)d * BUFSZ;
        const uint32_t a0 = buf + (uint32_t)gr * ROWSTR + (uint32_t)((ln & 3) << 2);
#pragma unroll
        for (int gq = 0; gq < 8; ++gq) {            // 8 kt16-groups per 128-col chunk
            const uint32_t ae = a0 + (uint32_t)(gq << 6);   // 16 floats per group
            uint32_t Ae[4], Ao[4];
            Ae[0] = f2tf32(lds32(ae));
            Ae[1] = f2tf32(lds32(ae + 8 * ROWSTR));
            Ae[2] = f2tf32(lds32(ae + 16));
            Ae[3] = f2tf32(lds32(ae + 8 * ROWSTR + 16));
            Ao[0] = f2tf32(lds32(ae + 32));
            Ao[1] = f2tf32(lds32(ae + 8 * ROWSTR + 32));
            Ao[2] = f2tf32(lds32(ae + 48));
            Ao[3] = f2tf32(lds32(ae + 8 * ROWSTR + 48));

            const uint4* bp = &g_W1F[(((kc << 3) + gq) << 2) * 32 + ln];
            uint4 bf[4];
#pragma unroll
            for (int nt = 0; nt < 4; ++nt) bf[nt] = __ldg(bp + nt * 32);
#pragma unroll
            for (int nt = 0; nt < 4; ++nt) mma_tf32(acc1[nt], Ae, bf[nt].x, bf[nt].y);
#pragma unroll
            for (int nt = 0; nt < 4; ++nt) mma_tf32(acc1[nt], Ao, bf[nt].z, bf[nt].w);
        }
    };

    stage(0, 0);
    stage(1, 1);
#pragma unroll
    for (int c = 0; c < 6; ++c) {
        if (c < 5) { CP_WAIT(1); } else { CP_WAIT(0); }
        __syncwarp();
        consume(c, c & 1);
        if (c < 4) stage(c + 2, c & 1);
    }
    CP_WAIT(0);
    __syncwarp();

    // ---------------- H (fp32 C-frags) -> G23 tf32 A-frags via shfl ----------------
    // Afr[q][0] = H(gr, 8q+(ln&3)); [1] row+8; [2] col+4; [3] row+8,col+4.
    uint32_t Afr[4][4];
    {
        const int srcA = (ln & 0x1C) | ((ln & 3) >> 1);
        const int srcB = srcA + 2;
        const bool hi = (ln & 1);
#pragma unroll
        for (int q = 0; q < 4; ++q) {
            const float e0 = __shfl_sync(0xFFFFFFFFu, acc1[q][0], srcA);
            const float e1 = __shfl_sync(0xFFFFFFFFu, acc1[q][1], srcA);
            const float e2 = __shfl_sync(0xFFFFFFFFu, acc1[q][2], srcA);
            const float e3 = __shfl_sync(0xFFFFFFFFu, acc1[q][3], srcA);
            const float f0 = __shfl_sync(0xFFFFFFFFu, acc1[q][0], srcB);
            const float f1 = __shfl_sync(0xFFFFFFFFu, acc1[q][1], srcB);
            const float f2 = __shfl_sync(0xFFFFFFFFu, acc1[q][2], srcB);
            const float f3 = __shfl_sync(0xFFFFFFFFu, acc1[q][3], srcB);
            Afr[q][0] = f2tf32(hi ? e1 : e0);
            Afr[q][1] = f2tf32(hi ? e3 : e2);
            Afr[q][2] = f2tf32(hi ? f1 : f0);
            Afr[q][3] = f2tf32(hi ? f3 : f2);
        }
    }

    // ---------------- G23: 6 groups of 16 n-tiles (128 cols), smem-staged epilogue --
    const uint32_t rbuf = wbuf;                       // result tile: 16 rows x 132 floats
    const uint32_t stsA = rbuf + (uint32_t)gr * ROWSTR + (uint32_t)(q2 << 2);
    const uint32_t stsB = stsA + 8 * ROWSTR;

    for (int gidx = 0; gidx < 6; ++gidx) {
#pragma unroll 4
        for (int tt = 0; tt < 16; ++tt) {
            const int nt = gidx * 16 + tt;
            const uint4 p0 = __ldg(&g_W23F[((nt << 1) + 0) * 32 + ln]);
            const uint4 p1 = __ldg(&g_W23F[((nt << 1) + 1) * 32 + ln]);
            float c[4] = {0.f, 0.f, 0.f, 0.f};
            mma_tf32(c, Afr[0], p0.x, p0.y);
            mma_tf32(c, Afr[1], p0.z, p0.w);
            mma_tf32(c, Afr[2], p1.x, p1.y);
            mma_tf32(c, Afr[3], p1.z, p1.w);

            const uint32_t coff = (uint32_t)(tt << 5);       // tt*8 floats
            sts64(stsA + coff, c[0], c[1]);
            sts64(stsB + coff, c[2], c[3]);
        }
        __syncwarp();

        // coalesced write-out: one full row (128 cols) per instruction
        const int gcol = gidx * 128 + (ln << 2);
        const float4 be = __ldg((const float4*)(g_beff + gcol));
        const uint32_t rdbase = rbuf + (uint32_t)(ln << 4);
#pragma unroll
        for (int lr = 0; lr < 16; ++lr) {
            const int R = r0 + wr0 + lr;
            const int b = R / 196;
            const int p = R - b * 196;
            const float4 rv = lds128(rdbase + (uint32_t)lr * ROWSTR);
            const float4 pv = __ldg((const float4*)(pos + (p + 1) * 768 + gcol));
            float4 o;
            o.x = rv.x + pv.x + be.x;
            o.y = rv.y + pv.y + be.y;
            o.z = rv.z + pv.z + be.z;
            o.w = rv.w + pv.w + be.w;
            *(float4*)(out + ((size_t)b * 197 + p + 1) * 768 + gcol) = o;
        }
        __syncwarp();   // protect tile before next group's STS
    }
}

extern "C" void kernel_launch(void* const* d_in, const int* in_sizes, int n_in,
                              void* d_out, int out_size)
{
    const float* X   = (const float*)d_in[0];
    const float* W1  = (const float*)d_in[1];
    const float* b1  = (const float*)d_in[2];
    const float* W2  = (const float*)d_in[3];
    const float* b2  = (const float*)d_in[4];
    const float* W3  = (const float*)d_in[5];
    const float* b3  = (const float*)d_in[6];
    const float* cls = (const float*)d_in[7];
    const float* pos = (const float*)d_in[8];
    float* out = (float*)d_out;

    const int smem = 4 * WSLOT;   // 67584 B
    cudaFuncSetAttribute(patch_embed_mma,
                         cudaFuncAttributeMaxDynamicSharedMemorySize, smem);

    prep_kernel<<<96, 256>>>(W1, b1, W2, b2, W3, b3, cls, pos, out);
    patch_embed_mma<<<392, THREADS, smem>>>(X, pos, out);
}